// round 2
// baseline (speedup 1.0000x reference)
#include <cuda_runtime.h>
#include <math.h>

#define PP 20000
#define TT 30
#define SS 1000
#define DD 128     // elem embedding dim
#define HH 128     // LSTM hidden
#define GG 512     // 4*H gate width
#define DPP 128    // proj out dim
#define EE 64      // leaf embedding dim

// ---------------- device scratch (static: no allocations allowed) ----------
__device__ float g_H[2][PP * HH];
__device__ float g_C[2][PP * HH];
__device__ float g_Z[2][(size_t)PP * GG];
__device__ float g_full[(size_t)PP * DPP];
__device__ float g_scores[PP];
__device__ int   g_mxe[SS];
__device__ float g_den[SS];
__device__ int   g_is64[2];   // [0]: path_elements is int64, [1]: leaf_idxs is int64

// ---------------- helpers --------------------------------------------------
__device__ __forceinline__ int encf(float f) {
    int i = __float_as_int(f);
    return i >= 0 ? i : (i ^ 0x7fffffff);
}
__device__ __forceinline__ float decf(int i) {
    return __int_as_float(i >= 0 ? i : (i ^ 0x7fffffff));
}

// ---------------- init + dtype detection -----------------------------------
__global__ void init_kernel(const void* pe, const void* li, float* out) {
    long long i = (long long)blockIdx.x * blockDim.x + threadIdx.x;
    const long long NH = 2LL * PP * HH;
    if (i < NH) {
        (&g_H[0][0])[i] = 0.f;
        (&g_C[0][0])[i] = 0.f;
    }
    long long j = i - NH;
    if (j >= 0 && j < PP) g_scores[j] = 0.f;
    j -= PP;
    if (j >= 0 && j < SS) {
        g_den[j] = 0.f;
        g_mxe[j] = (int)0x80000000;
    }
    j -= SS;
    if (j >= 0 && j < (long long)SS * DPP) out[j] = 0.f;

    if (i == 0) {
        // Detect int64 vs int32: indices are small nonneg values, so if the
        // buffer is int64 every odd 32-bit word is 0. 64 random values in
        // [0,10000) being all-zero as int32 is essentially impossible.
        int a = 1, b = 1;
        const int* p32 = (const int*)pe;
        const int* l32 = (const int*)li;
        for (int k = 0; k < 64; k++) {
            if (p32[2 * k + 1] != 0) a = 0;
            if (l32[2 * k + 1] != 0) b = 0;
        }
        g_is64[0] = a;
        g_is64[1] = b;
    }
}

// ---------------- LSTM step GEMM: z = [x_t | h] @ [W;U] --------------------
// grid: (ceil(P/64), 4 col-tiles of 128, 2 directions), 256 threads.
__global__ __launch_bounds__(256) void lstm_gemm(
    const float* __restrict__ emb, const void* __restrict__ pe,
    const float* __restrict__ Wf, const float* __restrict__ Uf,
    const float* __restrict__ Wb, const float* __restrict__ Ub,
    int t)
{
    const int dir = blockIdx.z;
    const int te  = dir ? (TT - 1 - t) : t;
    const float* Wm = dir ? Wb : Wf;
    const float* Um = dir ? Ub : Uf;
    const float* Hbuf = g_H[dir];
    const int p0 = blockIdx.x * 64;
    const int n0 = blockIdx.y * 128;
    const int tid = threadIdx.x;

    __shared__ float As[64][33];
    __shared__ float Bs[32][128];
    __shared__ int   sE[64];

    if (tid < 64) {
        int p = p0 + tid;
        if (p >= PP) p = PP - 1;
        long long e;
        if (g_is64[0]) e = ((const long long*)pe)[(long long)p * TT + te];
        else           e = ((const int*)pe)[p * TT + te];
        sE[tid] = (int)e;
    }
    __syncthreads();

    const int rg = tid >> 4;   // 0..15 -> rows rg*4..rg*4+3
    const int cg = tid & 15;   // 0..15 -> cols cg*8..cg*8+7
    float acc[4][8];
#pragma unroll
    for (int r = 0; r < 4; r++)
#pragma unroll
        for (int c = 0; c < 8; c++) acc[r][c] = 0.f;

    for (int ck = 0; ck < 8; ck++) {
        // load A tile (64 rows x 32 k) : gather x_t from embeddings, h from state
#pragma unroll
        for (int j = 0; j < 8; j++) {
            int idx = tid + j * 256;
            int r = idx >> 5, kk = idx & 31;
            int gk = ck * 32 + kk;
            float v;
            if (gk < 128) {
                v = emb[(size_t)sE[r] * DD + gk];
            } else {
                int p = p0 + r;
                if (p >= PP) p = PP - 1;
                v = Hbuf[(size_t)p * HH + (gk - 128)];
            }
            As[r][kk] = v;
        }
        // load B tile (32 k x 128 cols) from stacked [W;U]
#pragma unroll
        for (int j = 0; j < 16; j++) {
            int idx = tid + j * 256;
            int kk = idx >> 7, c = idx & 127;
            int gk = ck * 32 + kk;
            float v = (gk < 128) ? Wm[(size_t)gk * GG + n0 + c]
                                 : Um[(size_t)(gk - 128) * GG + n0 + c];
            Bs[kk][c] = v;
        }
        __syncthreads();
#pragma unroll
        for (int kk = 0; kk < 32; kk++) {
            float a0 = As[rg * 4 + 0][kk];
            float a1 = As[rg * 4 + 1][kk];
            float a2 = As[rg * 4 + 2][kk];
            float a3 = As[rg * 4 + 3][kk];
            float4 bA = *(const float4*)&Bs[kk][cg * 8];
            float4 bB = *(const float4*)&Bs[kk][cg * 8 + 4];
            float bv[8] = {bA.x, bA.y, bA.z, bA.w, bB.x, bB.y, bB.z, bB.w};
#pragma unroll
            for (int c = 0; c < 8; c++) {
                acc[0][c] += a0 * bv[c];
                acc[1][c] += a1 * bv[c];
                acc[2][c] += a2 * bv[c];
                acc[3][c] += a3 * bv[c];
            }
        }
        __syncthreads();
    }

    float* Zd = g_Z[dir];
#pragma unroll
    for (int r = 0; r < 4; r++) {
        int p = p0 + rg * 4 + r;
        if (p < PP) {
            float4 v0 = make_float4(acc[r][0], acc[r][1], acc[r][2], acc[r][3]);
            float4 v1 = make_float4(acc[r][4], acc[r][5], acc[r][6], acc[r][7]);
            *(float4*)&Zd[(size_t)p * GG + n0 + cg * 8]     = v0;
            *(float4*)&Zd[(size_t)p * GG + n0 + cg * 8 + 4] = v1;
        }
    }
}

// ---------------- gate nonlinearities + masked state update ----------------
__global__ void lstm_gate(const float* __restrict__ bf, const float* __restrict__ bb,
                          const int* __restrict__ lens, int t)
{
    const int dir = blockIdx.y;
    int idx = blockIdx.x * 256 + threadIdx.x;
    if (idx >= PP * HH) return;
    int p = idx >> 7, j = idx & 127;
    int te = dir ? (TT - 1 - t) : t;
    if (te >= lens[p]) return;   // masked step: carry state (Keras semantics)
    const float* bias = dir ? bb : bf;
    const float* z = &g_Z[dir][(size_t)p * GG];
    float zi = z[j]       + bias[j];
    float zf = z[128 + j] + bias[128 + j];
    float zg = z[256 + j] + bias[256 + j];
    float zo = z[384 + j] + bias[384 + j];
    float ig = 1.f / (1.f + expf(-zi));
    float fg = 1.f / (1.f + expf(-zf));
    float gg = tanhf(zg);
    float og = 1.f / (1.f + expf(-zo));
    float c  = g_C[dir][idx];
    float cn = fg * c + ig * gg;
    g_C[dir][idx] = cn;
    g_H[dir][idx] = og * tanhf(cn);
}

// ---------------- proj GEMM: full = [leaf0|leaf1|h_f|h_b] @ proj, + scores --
__global__ __launch_bounds__(256) void proj_kernel(
    const float* __restrict__ leafE, const void* __restrict__ li,
    const float* __restrict__ proj, const float* __restrict__ att)
{
    const int p0 = blockIdx.x * 64;
    const int tid = threadIdx.x;
    __shared__ float As[64][33];
    __shared__ float Bs[32][128];
    __shared__ int   sL[64][2];

    if (tid < 128) {
        int r = tid >> 1, which = tid & 1;
        int p = p0 + r;
        if (p >= PP) p = PP - 1;
        long long v;
        if (g_is64[1]) v = ((const long long*)li)[(long long)p * 2 + which];
        else           v = ((const int*)li)[p * 2 + which];
        sL[r][which] = (int)v;
    }
    __syncthreads();

    const int rg = tid >> 4;
    const int cg = tid & 15;
    float acc[4][8];
#pragma unroll
    for (int r = 0; r < 4; r++)
#pragma unroll
        for (int c = 0; c < 8; c++) acc[r][c] = 0.f;

    for (int ck = 0; ck < 12; ck++) {   // K = 384
#pragma unroll
        for (int j = 0; j < 8; j++) {
            int idx = tid + j * 256;
            int r = idx >> 5, kk = idx & 31;
            int gk = ck * 32 + kk;
            int p = p0 + r;
            if (p >= PP) p = PP - 1;
            float v;
            if (gk < 64)        v = leafE[(size_t)sL[r][0] * EE + gk];
            else if (gk < 128)  v = leafE[(size_t)sL[r][1] * EE + (gk - 64)];
            else if (gk < 256)  v = g_H[0][(size_t)p * HH + (gk - 128)];
            else                v = g_H[1][(size_t)p * HH + (gk - 256)];
            As[r][kk] = v;
        }
#pragma unroll
        for (int j = 0; j < 16; j++) {
            int idx = tid + j * 256;
            int kk = idx >> 7, c = idx & 127;
            int gk = ck * 32 + kk;
            Bs[kk][c] = proj[(size_t)gk * DPP + c];
        }
        __syncthreads();
#pragma unroll
        for (int kk = 0; kk < 32; kk++) {
            float a0 = As[rg * 4 + 0][kk];
            float a1 = As[rg * 4 + 1][kk];
            float a2 = As[rg * 4 + 2][kk];
            float a3 = As[rg * 4 + 3][kk];
            float4 bA = *(const float4*)&Bs[kk][cg * 8];
            float4 bB = *(const float4*)&Bs[kk][cg * 8 + 4];
            float bv[8] = {bA.x, bA.y, bA.z, bA.w, bB.x, bB.y, bB.z, bB.w};
#pragma unroll
            for (int c = 0; c < 8; c++) {
                acc[0][c] += a0 * bv[c];
                acc[1][c] += a1 * bv[c];
                acc[2][c] += a2 * bv[c];
                acc[3][c] += a3 * bv[c];
            }
        }
        __syncthreads();
    }

#pragma unroll
    for (int r = 0; r < 4; r++) {
        int p = p0 + rg * 4 + r;
        if (p < PP) {
            float s = 0.f;
#pragma unroll
            for (int c = 0; c < 8; c++) s += acc[r][c] * att[cg * 8 + c];
            float4 v0 = make_float4(acc[r][0], acc[r][1], acc[r][2], acc[r][3]);
            float4 v1 = make_float4(acc[r][4], acc[r][5], acc[r][6], acc[r][7]);
            *(float4*)&g_full[(size_t)p * DPP + cg * 8]     = v0;
            *(float4*)&g_full[(size_t)p * DPP + cg * 8 + 4] = v1;
            atomicAdd(&g_scores[p], s);
        }
    }
}

// ---------------- segment softmax + weighted accumulation ------------------
__global__ void seg_max_k(const int* __restrict__ seg) {
    int p = blockIdx.x * 256 + threadIdx.x;
    if (p < PP) atomicMax(&g_mxe[seg[p]], encf(g_scores[p]));
}
__global__ void seg_den_k(const int* __restrict__ seg) {
    int p = blockIdx.x * 256 + threadIdx.x;
    if (p < PP) {
        int s = seg[p];
        atomicAdd(&g_den[s], expf(g_scores[p] - decf(g_mxe[s])));
    }
}
__global__ void seg_out_k(const int* __restrict__ seg, float* __restrict__ out) {
    int idx = blockIdx.x * 256 + threadIdx.x;
    if (idx < PP * DPP) {
        int p = idx >> 7, j = idx & 127;
        int s = seg[p];
        float w = expf(g_scores[p] - decf(g_mxe[s])) / g_den[s];
        atomicAdd(&out[(size_t)s * DPP + j], w * g_full[idx]);
    }
}

// ---------------- launch ----------------------------------------------------
extern "C" void kernel_launch(void* const* d_in, const int* in_sizes, int n_in,
                              void* d_out, int out_size)
{
    (void)in_sizes; (void)n_in; (void)out_size;
    const float* leafE = (const float*)d_in[0];
    const float* emb   = (const float*)d_in[1];
    const float* Wf    = (const float*)d_in[2];
    const float* Uf    = (const float*)d_in[3];
    const float* bf    = (const float*)d_in[4];
    const float* Wb    = (const float*)d_in[5];
    const float* Ub    = (const float*)d_in[6];
    const float* bb    = (const float*)d_in[7];
    const float* proj  = (const float*)d_in[8];
    const float* att   = (const float*)d_in[9];
    const void*  pe    = d_in[10];
    const int*   lens  = (const int*)d_in[11];
    const void*  li    = d_in[12];
    const int*   seg   = (const int*)d_in[13];
    float* out = (float*)d_out;

    const long long initN = 2LL * PP * HH + PP + SS + (long long)SS * DPP;
    init_kernel<<<(unsigned)((initN + 255) / 256), 256>>>(pe, li, out);

    dim3 ggrid((PP + 63) / 64, 4, 2);
    dim3 gategrid((PP * HH + 255) / 256, 2);
    for (int t = 0; t < TT; t++) {
        lstm_gemm<<<ggrid, 256>>>(emb, pe, Wf, Uf, Wb, Ub, t);
        lstm_gate<<<gategrid, 256>>>(bf, bb, lens, t);
    }
    proj_kernel<<<(PP + 63) / 64, 256>>>(leafE, li, proj, att);
    seg_max_k<<<(PP + 255) / 256, 256>>>(seg);
    seg_den_k<<<(PP + 255) / 256, 256>>>(seg);
    seg_out_k<<<(PP * DPP + 255) / 256, 256>>>(seg, out);
}

// round 3
// speedup vs baseline: 5.3609x; 5.3609x over previous
#include <cuda_runtime.h>
#include <math.h>

#define PP 20000
#define TT 30
#define SS 1000
#define DD 128     // elem embedding dim
#define HH 128     // LSTM hidden
#define GG 512     // 4*H gate width
#define DPP 128    // proj out dim
#define EE 64      // leaf embedding dim

// ---------------- device scratch (static: no allocations allowed) ----------
__device__ float g_Hp[2][PP * HH];            // hidden state, PERMUTED row order
__device__ float g_Cp[2][PP * HH];            // cell state, PERMUTED
__device__ float g_Z[2][(size_t)PP * GG];     // gate preacts, PERMUTED
__device__ float g_Br[2][256 * GG];           // tf32-rounded [W;U] per dir
__device__ float g_full[(size_t)PP * DPP];    // PERMUTED
__device__ float g_scores[PP];                // PERMUTED
__device__ int   g_mxe[SS];
__device__ float g_den[SS];
__device__ int   g_is64[2];
__device__ int   g_hist[TT + 2];
__device__ int   g_off[TT + 2];
__device__ int   g_perm[PP];                  // permuted row -> original path
__device__ int   g_cnt[TT];                   // #paths with len > s

// ---------------- helpers --------------------------------------------------
__device__ __forceinline__ int encf(float f) {
    int i = __float_as_int(f);
    return i >= 0 ? i : (i ^ 0x7fffffff);
}
__device__ __forceinline__ float decf(int i) {
    return __int_as_float(i >= 0 ? i : (i ^ 0x7fffffff));
}
__device__ __forceinline__ float totf(float x) {
    unsigned u;
    asm("cvt.rna.tf32.f32 %0, %1;" : "=r"(u) : "f"(x));
    return __uint_as_float(u);
}
__device__ __forceinline__ void mma_tf32(float* c, const unsigned* a, const unsigned* b) {
    asm volatile(
        "mma.sync.aligned.m16n8k8.row.col.f32.tf32.tf32.f32 "
        "{%0,%1,%2,%3}, {%4,%5,%6,%7}, {%8,%9}, {%0,%1,%2,%3};"
        : "+f"(c[0]), "+f"(c[1]), "+f"(c[2]), "+f"(c[3])
        : "r"(a[0]), "r"(a[1]), "r"(a[2]), "r"(a[3]), "r"(b[0]), "r"(b[1]));
}

// ---------------- init + dtype detection -----------------------------------
__global__ void init_kernel(const void* pe, const void* li, float* out) {
    long long i = (long long)blockIdx.x * blockDim.x + threadIdx.x;
    const long long NH = 2LL * PP * HH;
    if (i < NH) {
        (&g_Hp[0][0])[i] = 0.f;
        (&g_Cp[0][0])[i] = 0.f;
    }
    long long j = i - NH;
    if (j >= 0 && j < PP) g_scores[j] = 0.f;
    j -= PP;
    if (j >= 0 && j < SS) {
        g_den[j] = 0.f;
        g_mxe[j] = (int)0x80000000;
    }
    j -= SS;
    if (j >= 0 && j < (long long)SS * DPP) out[j] = 0.f;
    j -= (long long)SS * DPP;
    if (j >= 0 && j < TT + 2) g_hist[j] = 0;

    if (i == 0) {
        int a = 1, b = 1;
        const int* p32 = (const int*)pe;
        const int* l32 = (const int*)li;
        for (int k = 0; k < 64; k++) {
            if (p32[2 * k + 1] != 0) a = 0;
            if (l32[2 * k + 1] != 0) b = 0;
        }
        g_is64[0] = a;
        g_is64[1] = b;
    }
}

// ---------------- counting sort by length (descending) ----------------------
__global__ void hist_k(const int* __restrict__ lens) {
    int p = blockIdx.x * 256 + threadIdx.x;
    if (p < PP) {
        int L = lens[p];
        if (L < 0) L = 0;
        if (L > TT) L = TT;
        atomicAdd(&g_hist[L], 1);
    }
}
__global__ void scan_k() {
    if (threadIdx.x == 0 && blockIdx.x == 0) {
        int run = 0;
        for (int L = TT; L >= 0; --L) {
            g_off[L] = run;
            run += g_hist[L];
        }
        for (int s = 0; s < TT; s++) {
            int c = 0;
            for (int L = s + 1; L <= TT; L++) c += g_hist[L];
            g_cnt[s] = c;
        }
    }
}
__global__ void scatter_k(const int* __restrict__ lens) {
    int p = blockIdx.x * 256 + threadIdx.x;
    if (p < PP) {
        int L = lens[p];
        if (L < 0) L = 0;
        if (L > TT) L = TT;
        int slot = atomicAdd(&g_off[L], 1);
        g_perm[slot] = p;
    }
}

// ---------------- pre-round weights to tf32 ---------------------------------
__global__ void bround_k(const float* __restrict__ Wf, const float* __restrict__ Uf,
                         const float* __restrict__ Wb, const float* __restrict__ Ub)
{
    int i = blockIdx.x * 256 + threadIdx.x;
    if (i >= 2 * 256 * GG) return;
    int dir = i / (256 * GG);
    int r = i - dir * (256 * GG);
    int k = r / GG, n = r - k * GG;
    const float* W = dir ? Wb : Wf;
    const float* U = dir ? Ub : Uf;
    float v = (k < 128) ? W[(size_t)k * GG + n] : U[(size_t)(k - 128) * GG + n];
    g_Br[dir][r] = totf(v);
}

// ---------------- LSTM step GEMM on tensor cores (tf32 mma) -----------------
// C[128 x 128] tile: z[p, n] = [x_t | h] @ [W;U], permuted rows, active prefix.
// grid: (157, 4, 2), 256 threads = 8 warps (4 M x 2 N), warp tile 32x64.
__global__ __launch_bounds__(256, 2) void lstm_mma(
    const float* __restrict__ emb, const void* __restrict__ pe, int t)
{
    const int dir = blockIdx.z;
    const int s   = dir ? (TT - 1 - t) : t;
    const int cnt = g_cnt[s];
    const int p0  = blockIdx.x * 128;
    if (p0 >= cnt) return;
    const int n0  = blockIdx.y * 128;
    const int tid = threadIdx.x;

    __shared__ float As[128][36];
    __shared__ float Bs[32][136];
    __shared__ int   sE[128];

    if (tid < 128) {
        int p = p0 + tid;
        if (p >= PP) p = PP - 1;
        int orig = g_perm[p];
        long long e;
        if (g_is64[0]) e = ((const long long*)pe)[(long long)orig * TT + s];
        else           e = ((const int*)pe)[orig * TT + s];
        sE[tid] = (int)e;
    }
    __syncthreads();

    const int warp = tid >> 5, lane = tid & 31;
    const int grp = lane >> 2, tig = lane & 3;
    const int wm = warp >> 1, wn = warp & 1;
    const float* Hb = g_Hp[dir];
    const float* Bw = g_Br[dir];

    float acc[2][8][4];
#pragma unroll
    for (int mt = 0; mt < 2; mt++)
#pragma unroll
        for (int nt = 0; nt < 8; nt++)
#pragma unroll
            for (int q = 0; q < 4; q++) acc[mt][nt][q] = 0.f;

    for (int ck = 0; ck < 8; ck++) {
        const int k0 = ck * 32;
        // A tile: 128 rows x 32 k (gather x from emb / h from state), round to tf32
#pragma unroll
        for (int it = 0; it < 4; it++) {
            int idx = tid + it * 256;          // 0..1023 float4s
            int r = idx >> 3, kk = (idx & 7) * 4;
            int gk = k0 + kk;
            float4 v;
            if (gk < 128) {
                v = *(const float4*)&emb[(size_t)sE[r] * DD + gk];
            } else {
                int p = p0 + r;
                if (p >= PP) p = PP - 1;
                v = *(const float4*)&Hb[(size_t)p * HH + (gk - 128)];
            }
            float4 w = make_float4(totf(v.x), totf(v.y), totf(v.z), totf(v.w));
            *(float4*)&As[r][kk] = w;
        }
        // B tile: 32 k x 128 n (already tf32-rounded)
#pragma unroll
        for (int it = 0; it < 4; it++) {
            int idx = tid + it * 256;
            int kk = idx >> 5, c = (idx & 31) * 4;
            float4 v = *(const float4*)&Bw[(size_t)(k0 + kk) * GG + n0 + c];
            *(float4*)&Bs[kk][c] = v;
        }
        __syncthreads();

#pragma unroll
        for (int k8 = 0; k8 < 4; k8++) {
            const int kb = k8 * 8;
            unsigned a[2][4], b[8][2];
#pragma unroll
            for (int mt = 0; mt < 2; mt++) {
                int rb = wm * 32 + mt * 16;
                a[mt][0] = __float_as_uint(As[rb + grp][kb + tig]);
                a[mt][1] = __float_as_uint(As[rb + grp + 8][kb + tig]);
                a[mt][2] = __float_as_uint(As[rb + grp][kb + tig + 4]);
                a[mt][3] = __float_as_uint(As[rb + grp + 8][kb + tig + 4]);
            }
#pragma unroll
            for (int nt = 0; nt < 8; nt++) {
                int cb = wn * 64 + nt * 8 + grp;
                b[nt][0] = __float_as_uint(Bs[kb + tig][cb]);
                b[nt][1] = __float_as_uint(Bs[kb + tig + 4][cb]);
            }
#pragma unroll
            for (int mt = 0; mt < 2; mt++)
#pragma unroll
                for (int nt = 0; nt < 8; nt++)
                    mma_tf32(acc[mt][nt], a[mt], b[nt]);
        }
        __syncthreads();
    }

    // epilogue: write active rows only
    float* Zd = g_Z[dir];
#pragma unroll
    for (int mt = 0; mt < 2; mt++) {
        int pr0 = p0 + wm * 32 + mt * 16 + grp;
#pragma unroll
        for (int nt = 0; nt < 8; nt++) {
            int col = n0 + wn * 64 + nt * 8 + tig * 2;
            if (pr0 < cnt)
                *(float2*)&Zd[(size_t)pr0 * GG + col] =
                    make_float2(acc[mt][nt][0], acc[mt][nt][1]);
            if (pr0 + 8 < cnt)
                *(float2*)&Zd[(size_t)(pr0 + 8) * GG + col] =
                    make_float2(acc[mt][nt][2], acc[mt][nt][3]);
        }
    }
}

// ---------------- gate nonlinearities + state update (active prefix) --------
__global__ void lstm_gate(const float* __restrict__ bf, const float* __restrict__ bb,
                          int t)
{
    const int dir = blockIdx.y;
    const int s   = dir ? (TT - 1 - t) : t;
    const int cnt = g_cnt[s];
    if ((int)(blockIdx.x * 2) >= cnt) return;   // 256 threads cover 2 rows
    int idx = blockIdx.x * 256 + threadIdx.x;
    int p = idx >> 7, j = idx & 127;
    if (p >= cnt) return;
    const float* bias = dir ? bb : bf;
    const float* z = &g_Z[dir][(size_t)p * GG];
    float zi = z[j]       + bias[j];
    float zf = z[128 + j] + bias[128 + j];
    float zg = z[256 + j] + bias[256 + j];
    float zo = z[384 + j] + bias[384 + j];
    float ig = 1.f / (1.f + expf(-zi));
    float fg = 1.f / (1.f + expf(-zf));
    float gg = tanhf(zg);
    float og = 1.f / (1.f + expf(-zo));
    float c  = g_Cp[dir][idx];
    float cn = fg * c + ig * gg;
    g_Cp[dir][idx] = cn;
    g_Hp[dir][idx] = og * tanhf(cn);
}

// ---------------- proj GEMM: full = [leaf0|leaf1|h_f|h_b] @ proj, + scores --
__global__ __launch_bounds__(256) void proj_kernel(
    const float* __restrict__ leafE, const void* __restrict__ li,
    const float* __restrict__ proj, const float* __restrict__ att)
{
    const int p0 = blockIdx.x * 64;
    const int tid = threadIdx.x;
    __shared__ float As[64][33];
    __shared__ float Bs[32][128];
    __shared__ int   sL[64][2];

    if (tid < 128) {
        int r = tid >> 1, which = tid & 1;
        int p = p0 + r;
        if (p >= PP) p = PP - 1;
        int orig = g_perm[p];
        long long v;
        if (g_is64[1]) v = ((const long long*)li)[(long long)orig * 2 + which];
        else           v = ((const int*)li)[orig * 2 + which];
        sL[r][which] = (int)v;
    }
    __syncthreads();

    const int rg = tid >> 4;
    const int cg = tid & 15;
    float acc[4][8];
#pragma unroll
    for (int r = 0; r < 4; r++)
#pragma unroll
        for (int c = 0; c < 8; c++) acc[r][c] = 0.f;

    for (int ck = 0; ck < 12; ck++) {   // K = 384
#pragma unroll
        for (int j = 0; j < 8; j++) {
            int idx = tid + j * 256;
            int r = idx >> 5, kk = idx & 31;
            int gk = ck * 32 + kk;
            int p = p0 + r;
            if (p >= PP) p = PP - 1;
            float v;
            if (gk < 64)        v = leafE[(size_t)sL[r][0] * EE + gk];
            else if (gk < 128)  v = leafE[(size_t)sL[r][1] * EE + (gk - 64)];
            else if (gk < 256)  v = g_Hp[0][(size_t)p * HH + (gk - 128)];
            else                v = g_Hp[1][(size_t)p * HH + (gk - 256)];
            As[r][kk] = v;
        }
#pragma unroll
        for (int j = 0; j < 16; j++) {
            int idx = tid + j * 256;
            int kk = idx >> 7, c = idx & 127;
            int gk = ck * 32 + kk;
            Bs[kk][c] = proj[(size_t)gk * DPP + c];
        }
        __syncthreads();
#pragma unroll
        for (int kk = 0; kk < 32; kk++) {
            float a0 = As[rg * 4 + 0][kk];
            float a1 = As[rg * 4 + 1][kk];
            float a2 = As[rg * 4 + 2][kk];
            float a3 = As[rg * 4 + 3][kk];
            float4 bA = *(const float4*)&Bs[kk][cg * 8];
            float4 bB = *(const float4*)&Bs[kk][cg * 8 + 4];
            float bv[8] = {bA.x, bA.y, bA.z, bA.w, bB.x, bB.y, bB.z, bB.w};
#pragma unroll
            for (int c = 0; c < 8; c++) {
                acc[0][c] += a0 * bv[c];
                acc[1][c] += a1 * bv[c];
                acc[2][c] += a2 * bv[c];
                acc[3][c] += a3 * bv[c];
            }
        }
        __syncthreads();
    }

#pragma unroll
    for (int r = 0; r < 4; r++) {
        int p = p0 + rg * 4 + r;
        if (p < PP) {
            float s = 0.f;
#pragma unroll
            for (int c = 0; c < 8; c++) s += acc[r][c] * att[cg * 8 + c];
            float4 v0 = make_float4(acc[r][0], acc[r][1], acc[r][2], acc[r][3]);
            float4 v1 = make_float4(acc[r][4], acc[r][5], acc[r][6], acc[r][7]);
            *(float4*)&g_full[(size_t)p * DPP + cg * 8]     = v0;
            *(float4*)&g_full[(size_t)p * DPP + cg * 8 + 4] = v1;
            atomicAdd(&g_scores[p], s);
        }
    }
}

// ---------------- segment softmax + weighted accumulation ------------------
__global__ void seg_max_k(const int* __restrict__ seg) {
    int p = blockIdx.x * 256 + threadIdx.x;
    if (p < PP) atomicMax(&g_mxe[seg[g_perm[p]]], encf(g_scores[p]));
}
__global__ void seg_den_k(const int* __restrict__ seg) {
    int p = blockIdx.x * 256 + threadIdx.x;
    if (p < PP) {
        int s = seg[g_perm[p]];
        atomicAdd(&g_den[s], expf(g_scores[p] - decf(g_mxe[s])));
    }
}
__global__ void seg_out_k(const int* __restrict__ seg, float* __restrict__ out) {
    int idx = blockIdx.x * 256 + threadIdx.x;
    if (idx < PP * DPP) {
        int p = idx >> 7, j = idx & 127;
        int s = seg[g_perm[p]];
        float w = expf(g_scores[p] - decf(g_mxe[s])) / g_den[s];
        atomicAdd(&out[(size_t)s * DPP + j], w * g_full[idx]);
    }
}

// ---------------- launch ----------------------------------------------------
extern "C" void kernel_launch(void* const* d_in, const int* in_sizes, int n_in,
                              void* d_out, int out_size)
{
    (void)in_sizes; (void)n_in; (void)out_size;
    const float* leafE = (const float*)d_in[0];
    const float* emb   = (const float*)d_in[1];
    const float* Wf    = (const float*)d_in[2];
    const float* Uf    = (const float*)d_in[3];
    const float* bf    = (const float*)d_in[4];
    const float* Wb    = (const float*)d_in[5];
    const float* Ub    = (const float*)d_in[6];
    const float* bb    = (const float*)d_in[7];
    const float* proj  = (const float*)d_in[8];
    const float* att   = (const float*)d_in[9];
    const void*  pe    = d_in[10];
    const int*   lens  = (const int*)d_in[11];
    const void*  li    = d_in[12];
    const int*   seg   = (const int*)d_in[13];
    float* out = (float*)d_out;

    const long long initN = 2LL * PP * HH + PP + SS + (long long)SS * DPP + TT + 2;
    init_kernel<<<(unsigned)((initN + 255) / 256), 256>>>(pe, li, out);
    hist_k<<<(PP + 255) / 256, 256>>>(lens);
    scan_k<<<1, 32>>>();
    scatter_k<<<(PP + 255) / 256, 256>>>(lens);
    bround_k<<<(2 * 256 * GG + 255) / 256, 256>>>(Wf, Uf, Wb, Ub);

    dim3 ggrid((PP + 127) / 128, 4, 2);
    dim3 gategrid((PP * HH + 255) / 256, 2);
    for (int t = 0; t < TT; t++) {
        lstm_mma<<<ggrid, 256>>>(emb, pe, t);
        lstm_gate<<<gategrid, 256>>>(bf, bb, t);
    }
    proj_kernel<<<(PP + 63) / 64, 256>>>(leafE, li, proj, att);
    seg_max_k<<<(PP + 255) / 256, 256>>>(seg);
    seg_den_k<<<(PP + 255) / 256, 256>>>(seg);
    seg_out_k<<<(PP * DPP + 255) / 256, 256>>>(seg, out);
}